// round 15
// baseline (speedup 1.0000x reference)
#include <cuda_runtime.h>
#include <cstdint>
#include <cstddef>

// Problem constants
#define BATCH  4
#define NSEQ   2048
#define DMODEL 1024
#define NHEAD  16
#define DKH    64
#define MROWS  (BATCH * NSEQ)   // 8192
#define NEGVAL (-1e11f)
#define KPAIRS 512              // DMODEL/2 bf16x2 pairs per row

// ---------------- scratch (device globals; no allocation allowed) ----------
__device__ float    g_Q[BATCH * NHEAD * NSEQ * DKH];   // (B,H,N,DK)
__device__ float    g_K[BATCH * NHEAD * NSEQ * DKH];
__device__ float    g_V[BATCH * NHEAD * NSEQ * DKH];
__device__ float    g_C[BATCH * NSEQ * DMODEL];        // attention context (B,N,D)
__device__ unsigned g_pmask[BATCH * NSEQ * NSEQ / 32]; // bit-packed mask
// globally packed bf16x2 k-pair arrays (hoisted split)
__device__ uint32_t g_XHp[3u * MROWS * KPAIRS];        // activations hi  (48MB)
__device__ uint32_t g_XLp[3u * MROWS * KPAIRS];        // activations lo
__device__ uint32_t g_WHp[4u * DMODEL * KPAIRS];       // weights hi, [n][kp]
__device__ uint32_t g_WLp[4u * DMODEL * KPAIRS];       // weights lo

// ---------------- helpers ---------------------------------------------------
__device__ __forceinline__ uint32_t f2tf32(float x) {
    uint32_t r;
    asm("cvt.rna.tf32.f32 %0, %1;" : "=r"(r) : "f"(x));
    return r;
}

__device__ __forceinline__ void mma_tf32(float* c, const uint32_t* a,
                                         uint32_t b0, uint32_t b1) {
    asm volatile(
        "mma.sync.aligned.m16n8k8.row.col.f32.tf32.tf32.f32 "
        "{%0,%1,%2,%3}, {%4,%5,%6,%7}, {%8,%9}, {%0,%1,%2,%3};"
        : "+f"(c[0]), "+f"(c[1]), "+f"(c[2]), "+f"(c[3])
        : "r"(a[0]), "r"(a[1]), "r"(a[2]), "r"(a[3]), "r"(b0), "r"(b1));
}

__device__ __forceinline__ void mma_bf16(float* c, const uint32_t* a,
                                         uint32_t b0, uint32_t b1) {
    asm volatile(
        "mma.sync.aligned.m16n8k16.row.col.f32.bf16.bf16.f32 "
        "{%0,%1,%2,%3}, {%4,%5,%6,%7}, {%8,%9}, {%0,%1,%2,%3};"
        : "+f"(c[0]), "+f"(c[1]), "+f"(c[2]), "+f"(c[3])
        : "r"(a[0]), "r"(a[1]), "r"(a[2]), "r"(a[3]), "r"(b0), "r"(b1));
}

// pack two floats to bf16x2: lo_val -> low half (lower k), hi_val -> high half
__device__ __forceinline__ uint32_t pack_bf16x2(float lo_val, float hi_val) {
    uint32_t r;
    asm("cvt.rn.bf16x2.f32 %0, %1, %2;" : "=r"(r) : "f"(hi_val), "f"(lo_val));
    return r;
}

__device__ __forceinline__ void cp16(uint32_t dst, const void* src) {
    asm volatile("cp.async.ca.shared.global [%0], [%1], 16;\n"
                 :: "r"(dst), "l"(src));
}
__device__ __forceinline__ void cp_commit() {
    asm volatile("cp.async.commit_group;\n");
}
template <int N>
__device__ __forceinline__ void cp_wait() {
    asm volatile("cp.async.wait_group %0;\n" :: "n"(N));
}
__device__ __forceinline__ uint32_t smem_u32(const void* p) {
    return (uint32_t)__cvta_generic_to_shared(p);
}

// ---------------- mask bit-pack ---------------------------------------------
__global__ void pack_mask_kernel(const int* __restrict__ mask) {
    int idx = blockIdx.x * blockDim.x + threadIdx.x;
    unsigned bit = (mask[idx] != 0) ? 1u : 0u;
    unsigned w = __ballot_sync(0xffffffffu, bit);
    if ((threadIdx.x & 31) == 0) g_pmask[idx >> 5] = w;
}

// ---------------- one-time bf16x2 split converts ----------------------------
// activations: [M][1024] fp32 -> [M][512] bf16x2 (hi) + residual (lo)
__global__ __launch_bounds__(256)
void convert_act_kernel(const float* __restrict__ in,
                        uint32_t* __restrict__ oh, uint32_t* __restrict__ ol) {
    int idx = blockIdx.x * 256 + threadIdx.x;       // m*512 + kp
    float2 v = ((const float2*)in)[idx];
    uint32_t hi = pack_bf16x2(v.x, v.y);
    float r0 = v.x - __uint_as_float(hi << 16);
    float r1 = v.y - __uint_as_float(hi & 0xffff0000u);
    oh[idx] = hi;
    ol[idx] = pack_bf16x2(r0, r1);
}

// weights: W[k][n] fp32 -> transposed packed [n][512] bf16x2 hi/lo
__global__ __launch_bounds__(256)
void convert_w_kernel(const float* __restrict__ in,
                      uint32_t* __restrict__ oh, uint32_t* __restrict__ ol) {
    int idx = blockIdx.x * 256 + threadIdx.x;       // n*512 + kp
    int n = idx >> 9, kp = idx & 511;
    float b0 = __ldg(&in[(size_t)(2 * kp) * DMODEL + n]);
    float b1 = __ldg(&in[(size_t)(2 * kp + 1) * DMODEL + n]);
    uint32_t hi = pack_bf16x2(b0, b1);
    float r0 = b0 - __uint_as_float(hi << 16);
    float r1 = b1 - __uint_as_float(hi & 0xffff0000u);
    oh[idx] = hi;
    ol[idx] = pack_bf16x2(r0, r1);
}

// ---------------- projection GEMM: 3xBF16, pre-packed, cp.async -------------
// C(8192x1024) = A @ W + bias.  Block tile 128x128, BK=16 (8 kp), 256 threads,
// 2x4 warp grid, warp tile 64x32.  Data pre-packed bf16x2: NO conversion in
// the hot loop (fixes R13's binder).  Two-phase mma bounds registers.
#define PST 12   // packed smem row stride (u32): banks 12*lg+lk all distinct
#define PROJ_SMEM (8 * 128 * PST * 4)   // 49152 B (4 arrays x 2 buffers)

template <bool SPLIT>
__device__ __forceinline__ void proj_core(const uint32_t* __restrict__ AHp,
                                          const uint32_t* __restrict__ ALp,
                                          const uint32_t* __restrict__ BHp,
                                          const uint32_t* __restrict__ BLp,
                                          const float* __restrict__ bias,
                                          float* __restrict__ out) {
    extern __shared__ uint32_t dsm[];
    uint32_t* sAH = dsm;                 // [2][128*PST]
    uint32_t* sAL = dsm + 2 * 128 * PST;
    uint32_t* sBH = dsm + 4 * 128 * PST;
    uint32_t* sBL = dsm + 6 * 128 * PST;

    const int tid = threadIdx.x;
    const int w = tid >> 5, l = tid & 31;
    const int lg = l >> 2, lk = l & 3;
    const int wm = (w >> 2) * 64;       // 0,64
    const int wn = (w & 3) * 32;        // 0,32,64,96
    const int m0 = blockIdx.y * 128, n0 = blockIdx.x * 128;

    const uint32_t aHaddr = smem_u32(sAH);
    const uint32_t aLaddr = smem_u32(sAL);
    const uint32_t bHaddr = smem_u32(sBH);
    const uint32_t bLaddr = smem_u32(sBL);

    // per-thread 16B chunk: row = tid>>1 (0..127), half = (tid&1)*4 kp
    const int crow = tid >> 1, chalf = (tid & 1) * 4;
    const uint32_t doff = (uint32_t)(crow * PST + chalf) * 4;
    const size_t asrc = (size_t)(m0 + crow) * KPAIRS + chalf;
    const size_t bsrc = (size_t)(n0 + crow) * KPAIRS + chalf;

    auto load_tile = [&](int kc, int buf) {
        uint32_t bo = buf * (128 * PST * 4);
        size_t ko = (size_t)kc * 8;
        cp16(aHaddr + bo + doff, AHp + asrc + ko);
        cp16(aLaddr + bo + doff, ALp + asrc + ko);
        cp16(bHaddr + bo + doff, BHp + bsrc + ko);
        cp16(bLaddr + bo + doff, BLp + bsrc + ko);
        cp_commit();
    };

    float c[4][4][4];
#pragma unroll
    for (int mi = 0; mi < 4; ++mi)
#pragma unroll
        for (int nj = 0; nj < 4; ++nj)
#pragma unroll
            for (int t = 0; t < 4; ++t) c[mi][nj][t] = 0.f;

    load_tile(0, 0);
    load_tile(1, 1);

    for (int it = 0; it < DMODEL / 16; ++it) {
        const uint32_t* cAH = sAH + (it & 1) * (128 * PST);
        const uint32_t* cAL = sAL + (it & 1) * (128 * PST);
        const uint32_t* cBH = sBH + (it & 1) * (128 * PST);
        const uint32_t* cBL = sBL + (it & 1) * (128 * PST);
        cp_wait<1>();
        __syncthreads();

        // ---- two-phase bf16 mma (one a[4][4] live at a time) ----
        uint32_t a[4][4];
        // phase 1: a = aH;  c += aH*bH + aH*bL
#pragma unroll
        for (int mi = 0; mi < 4; ++mi) {
            int mb = wm + 16 * mi + lg;
            a[mi][0] = cAH[mb * PST + lk];
            a[mi][1] = cAH[(mb + 8) * PST + lk];
            a[mi][2] = cAH[mb * PST + lk + 4];
            a[mi][3] = cAH[(mb + 8) * PST + lk + 4];
        }
#pragma unroll
        for (int nj = 0; nj < 4; ++nj) {
            int nb = wn + 8 * nj + lg;
            uint32_t bH0 = cBH[nb * PST + lk], bH1 = cBH[nb * PST + lk + 4];
            uint32_t bL0 = cBL[nb * PST + lk], bL1 = cBL[nb * PST + lk + 4];
#pragma unroll
            for (int mi = 0; mi < 4; ++mi) {
                mma_bf16(c[mi][nj], a[mi], bH0, bH1);
                mma_bf16(c[mi][nj], a[mi], bL0, bL1);
            }
        }
        // phase 2: a = aL;  c += aL*bH
#pragma unroll
        for (int mi = 0; mi < 4; ++mi) {
            int mb = wm + 16 * mi + lg;
            a[mi][0] = cAL[mb * PST + lk];
            a[mi][1] = cAL[(mb + 8) * PST + lk];
            a[mi][2] = cAL[mb * PST + lk + 4];
            a[mi][3] = cAL[(mb + 8) * PST + lk + 4];
        }
#pragma unroll
        for (int nj = 0; nj < 4; ++nj) {
            int nb = wn + 8 * nj + lg;
            uint32_t bH0 = cBH[nb * PST + lk], bH1 = cBH[nb * PST + lk + 4];
#pragma unroll
            for (int mi = 0; mi < 4; ++mi)
                mma_bf16(c[mi][nj], a[mi], bH0, bH1);
        }

        __syncthreads();
        if (it + 2 < DMODEL / 16) load_tile(it + 2, it & 1);
        else cp_commit();
    }

    // epilogue: bias + store (optionally remapped to (B,H,N,DK))
#pragma unroll
    for (int mi = 0; mi < 4; ++mi) {
#pragma unroll
        for (int nj = 0; nj < 4; ++nj) {
            int col = n0 + wn + 8 * nj + 2 * lk;
            float b0 = __ldg(&bias[col]), b1 = __ldg(&bias[col + 1]);
#pragma unroll
            for (int half = 0; half < 2; ++half) {
                int m = m0 + wm + 16 * mi + lg + 8 * half;
                float2 v;
                v.x = c[mi][nj][2 * half + 0] + b0;
                v.y = c[mi][nj][2 * half + 1] + b1;
                size_t idx;
                if (SPLIT) {
                    int b = m >> 11, row = m & 2047;
                    int h = col >> 6, dk = col & 63;
                    idx = (((size_t)(b * NHEAD + h) * NSEQ + row) * DKH + dk);
                } else {
                    idx = (size_t)m * DMODEL + col;
                }
                *(float2*)&out[idx] = v;
            }
        }
    }
}

__global__ __launch_bounds__(256)
void proj_qkv_kernel(const uint32_t* __restrict__ xh, const uint32_t* __restrict__ xl,
                     const uint32_t* __restrict__ wh, const uint32_t* __restrict__ wl,
                     const float* __restrict__ bq, const float* __restrict__ bk,
                     const float* __restrict__ bv,
                     float* __restrict__ oq, float* __restrict__ ok,
                     float* __restrict__ ov) {
    int z = blockIdx.z;
    const float* bias = (z == 0) ? bq : (z == 1) ? bk : bv;
    float* out = (z == 0) ? oq : (z == 1) ? ok : ov;
    proj_core<true>(xh + (size_t)z * MROWS * KPAIRS, xl + (size_t)z * MROWS * KPAIRS,
                    wh + (size_t)z * DMODEL * KPAIRS, wl + (size_t)z * DMODEL * KPAIRS,
                    bias, out);
}

__global__ __launch_bounds__(256)
void proj_out_kernel(const uint32_t* __restrict__ xh, const uint32_t* __restrict__ xl,
                     const uint32_t* __restrict__ wh, const uint32_t* __restrict__ wl,
                     const float* __restrict__ bias, float* __restrict__ out) {
    proj_core<false>(xh, xl, wh, wl, bias, out);
}

// ---------------- fused masked flash attention (R12 best, unchanged) --------
#define QPAD 68
#define KST  68
#define VST  72
#define ATTN_SMEM (128 * QPAD * 4 + 2 * 64 * KST * 4 + 2 * 64 * VST * 4 + 256 * 4)
__global__ __launch_bounds__(256)
void attn_kernel() {
    extern __shared__ char smraw[];
    uint32_t* Qs = (uint32_t*)smraw;                       // [128][QPAD] tf32
    float*    Ps = (float*)smraw;                          // aliases Qs
    float*    Kb = (float*)(smraw + 128 * QPAD * 4);       // [2][64][KST]
    float*    Vb = (float*)(smraw + 128 * QPAD * 4 + 2 * 64 * KST * 4);
    unsigned* Ms = (unsigned*)(smraw + 128 * QPAD * 4 + 2 * 64 * KST * 4
                               + 2 * 64 * VST * 4);        // [128][2]

    const int tid = threadIdx.x;
    const int w = tid >> 5, l = tid & 31;
    const int lg = l >> 2, lk = l & 3;
    const int rb = w * 16;
    const int bh = blockIdx.y;
    const int b = bh >> 4;
    const int h = bh & 15;
    const int q0 = blockIdx.x * 128;

    const float* Qg = g_Q + ((size_t)bh * NSEQ + q0) * DKH;
    const float* Kg = g_K + (size_t)bh * NSEQ * DKH;
    const float* Vg = g_V + (size_t)bh * NSEQ * DKH;

    const uint32_t KbAddr = smem_u32(Kb);
    const uint32_t VbAddr = smem_u32(Vb);

    auto load_kv = [&](int kt, int buf) {
        const float* Ksrc = Kg + (size_t)kt * 64 * DKH;
        const float* Vsrc = Vg + (size_t)kt * 64 * DKH;
        uint32_t kbase = KbAddr + buf * (64 * KST * 4);
        uint32_t vbase = VbAddr + buf * (64 * VST * 4);
#pragma unroll
        for (int i = 0; i < 4; ++i) {
            int ck = tid + 256 * i;
            int row = ck >> 4, c4 = (ck & 15) * 4;
            cp16(kbase + (row * KST + c4) * 4, Ksrc + row * DKH + c4);
            cp16(vbase + (row * VST + c4) * 4, Vsrc + row * DKH + c4);
        }
        cp_commit();
    };

#pragma unroll
    for (int i = 0; i < 8; ++i) {
        int v = tid + 256 * i;
        int row = v >> 4, d4 = (v & 15) * 4;
        float4 q = *(const float4*)(Qg + (size_t)row * DKH + d4);
        Qs[row * QPAD + d4 + 0] = f2tf32(q.x);
        Qs[row * QPAD + d4 + 1] = f2tf32(q.y);
        Qs[row * QPAD + d4 + 2] = f2tf32(q.z);
        Qs[row * QPAD + d4 + 3] = f2tf32(q.w);
    }
    __syncthreads();

    load_kv(0, 0);
    load_kv(1, 1);

    uint32_t qf[8][4];
#pragma unroll
    for (int ks = 0; ks < 8; ++ks) {
        qf[ks][0] = Qs[(rb + lg) * QPAD + ks * 8 + lk];
        qf[ks][1] = Qs[(rb + lg + 8) * QPAD + ks * 8 + lk];
        qf[ks][2] = Qs[(rb + lg) * QPAD + ks * 8 + lk + 4];
        qf[ks][3] = Qs[(rb + lg + 8) * QPAD + ks * 8 + lk + 4];
    }

    float m_run[2] = {-1e30f, -1e30f};
    float l_run[2] = {0.f, 0.f};

    float o[8][4];
#pragma unroll
    for (int nj = 0; nj < 8; ++nj)
#pragma unroll
        for (int t = 0; t < 4; ++t) o[nj][t] = 0.f;

    const int maskRowBase = b * NSEQ + q0;

    for (int kt = 0; kt < NSEQ / 64; ++kt) {
        float* K0 = Kb + (kt & 1) * (64 * KST);
        float* V0 = Vb + (kt & 1) * (64 * VST);

        cp_wait<1>();
        __syncthreads();

#pragma unroll
        for (int i = 0; i < 4; ++i) {
            int p = tid + 256 * i;
            int row = p >> 4, d4 = (p & 15) * 4;
            float4* ka = (float4*)&K0[row * KST + d4];
            float4 kv = *ka;
            uint4 kc = make_uint4(f2tf32(kv.x), f2tf32(kv.y), f2tf32(kv.z), f2tf32(kv.w));
            *(uint4*)ka = kc;
            float4* va = (float4*)&V0[row * VST + d4];
            float4 vv = *va;
            uint4 vc = make_uint4(f2tf32(vv.x), f2tf32(vv.y), f2tf32(vv.z), f2tf32(vv.w));
            *(uint4*)va = vc;
        }
        Ms[tid] = g_pmask[(size_t)(maskRowBase + (tid >> 1)) * (NSEQ / 32)
                          + kt * 2 + (tid & 1)];
        __syncthreads();

        float sc[8][4];
#pragma unroll
        for (int nj = 0; nj < 8; ++nj)
#pragma unroll
            for (int t = 0; t < 4; ++t) sc[nj][t] = 0.f;
#pragma unroll
        for (int ks = 0; ks < 8; ++ks) {
#pragma unroll
            for (int nj = 0; nj < 8; ++nj) {
                int nb = 8 * nj + lg;
                uint32_t b0 = __float_as_uint(K0[nb * KST + ks * 8 + lk]);
                uint32_t b1 = __float_as_uint(K0[nb * KST + ks * 8 + lk + 4]);
                mma_tf32(sc[nj], qf[ks], b0, b1);
            }
        }

#pragma unroll
        for (int r = 0; r < 2; ++r) {
            int row = rb + lg + 8 * r;
            unsigned mwA = Ms[row * 2], mwB = Ms[row * 2 + 1];
            int t0 = 2 * r;
            float rm = -1e30f;
#pragma unroll
            for (int nj = 0; nj < 8; ++nj) {
                int col = 8 * nj + 2 * lk;
                unsigned word = (nj < 4) ? mwA : mwB;
                float v0 = ((word >> (col & 31)) & 1u) ? sc[nj][t0] * 0.125f : NEGVAL;
                float v1 = ((word >> ((col + 1) & 31)) & 1u) ? sc[nj][t0 + 1] * 0.125f : NEGVAL;
                sc[nj][t0] = v0;
                sc[nj][t0 + 1] = v1;
                rm = fmaxf(rm, fmaxf(v0, v1));
            }
            rm = fmaxf(rm, __shfl_xor_sync(0xffffffffu, rm, 1));
            rm = fmaxf(rm, __shfl_xor_sync(0xffffffffu, rm, 2));
            float mn = fmaxf(m_run[r], rm);
            float corr = __expf(m_run[r] - mn);
            m_run[r] = mn;
            float ls = 0.f;
#pragma unroll
            for (int nj = 0; nj < 8; ++nj) {
                float p0 = __uint_as_float(f2tf32(__expf(sc[nj][t0] - mn)));
                float p1 = __uint_as_float(f2tf32(__expf(sc[nj][t0 + 1] - mn)));
                sc[nj][t0] = p0;
                sc[nj][t0 + 1] = p1;
                ls += p0 + p1;
            }
            ls += __shfl_xor_sync(0xffffffffu, ls, 1);
            ls += __shfl_xor_sync(0xffffffffu, ls, 2);
            l_run[r] = l_run[r] * corr + ls;
#pragma unroll
            for (int nj = 0; nj < 8; ++nj) {
                o[nj][t0] *= corr;
                o[nj][t0 + 1] *= corr;
            }
#pragma unroll
            for (int nj = 0; nj < 8; ++nj)
                *(float2*)&Ps[row * QPAD + 8 * nj + 2 * lk] =
                    make_float2(sc[nj][t0], sc[nj][t0 + 1]);
        }
        __syncwarp();

#pragma unroll
        for (int ks = 0; ks < 8; ++ks) {
            uint32_t af[4];
            af[0] = __float_as_uint(Ps[(rb + lg) * QPAD + ks * 8 + lk]);
            af[1] = __float_as_uint(Ps[(rb + lg + 8) * QPAD + ks * 8 + lk]);
            af[2] = __float_as_uint(Ps[(rb + lg) * QPAD + ks * 8 + lk + 4]);
            af[3] = __float_as_uint(Ps[(rb + lg + 8) * QPAD + ks * 8 + lk + 4]);
#pragma unroll
            for (int nj = 0; nj < 8; ++nj) {
                int nb = 8 * nj + lg;
                uint32_t b0 = __float_as_uint(V0[(ks * 8 + lk) * VST + nb]);
                uint32_t b1 = __float_as_uint(V0[(ks * 8 + lk + 4) * VST + nb]);
                mma_tf32(o[nj], af, b0, b1);
            }
        }

        __syncthreads();
        if (kt + 2 < NSEQ / 64) load_kv(kt + 2, kt & 1);
        else cp_commit();
    }

    float inv0 = 1.0f / l_run[0], inv1 = 1.0f / l_run[1];
    float* Cg = g_C + ((size_t)(b * NSEQ + q0)) * DMODEL + h * DKH;
#pragma unroll
    for (int nj = 0; nj < 8; ++nj) {
        int col = 8 * nj + 2 * lk;
        *(float2*)&Cg[(size_t)(rb + lg) * DMODEL + col] =
            make_float2(o[nj][0] * inv0, o[nj][1] * inv0);
        *(float2*)&Cg[(size_t)(rb + lg + 8) * DMODEL + col] =
            make_float2(o[nj][2] * inv1, o[nj][3] * inv1);
    }
}

// ---------------- launch ----------------------------------------------------
extern "C" void kernel_launch(void* const* d_in, const int* in_sizes, int n_in,
                              void* d_out, int out_size) {
    const float* query = (const float*)d_in[0];
    const float* key   = (const float*)d_in[1];
    const float* value = (const float*)d_in[2];
    const int*   mask  = (const int*)d_in[3];
    const float* Wq = (const float*)d_in[4];
    const float* bq = (const float*)d_in[5];
    const float* Wk = (const float*)d_in[6];
    const float* bk = (const float*)d_in[7];
    const float* Wv = (const float*)d_in[8];
    const float* bv = (const float*)d_in[9];
    const float* Wo = (const float*)d_in[10];
    const float* bo = (const float*)d_in[11];
    float* out = (float*)d_out;

    float *pQ, *pK, *pV, *pC;
    uint32_t *pXH, *pXL, *pWH, *pWL;
    cudaGetSymbolAddress((void**)&pQ, g_Q);
    cudaGetSymbolAddress((void**)&pK, g_K);
    cudaGetSymbolAddress((void**)&pV, g_V);
    cudaGetSymbolAddress((void**)&pC, g_C);
    cudaGetSymbolAddress((void**)&pXH, g_XHp);
    cudaGetSymbolAddress((void**)&pXL, g_XLp);
    cudaGetSymbolAddress((void**)&pWH, g_WHp);
    cudaGetSymbolAddress((void**)&pWL, g_WLp);

    const int ACT_P = MROWS * KPAIRS;     // packed elements per act matrix
    const int W_P = DMODEL * KPAIRS;      // packed elements per weight

    // 1) pack mask
    pack_mask_kernel<<<(BATCH * NSEQ * NSEQ) / 256, 256>>>(mask);

    // 2) one-time bf16x2 split converts
    convert_w_kernel<<<W_P / 256, 256>>>(Wq, pWH + 0 * W_P, pWL + 0 * W_P);
    convert_w_kernel<<<W_P / 256, 256>>>(Wk, pWH + 1 * W_P, pWL + 1 * W_P);
    convert_w_kernel<<<W_P / 256, 256>>>(Wv, pWH + 2 * W_P, pWL + 2 * W_P);
    convert_w_kernel<<<W_P / 256, 256>>>(Wo, pWH + 3 * W_P, pWL + 3 * W_P);
    convert_act_kernel<<<ACT_P / 256, 256>>>(query, pXH + 0 * (size_t)ACT_P,
                                             pXL + 0 * (size_t)ACT_P);
    convert_act_kernel<<<ACT_P / 256, 256>>>(key, pXH + 1 * (size_t)ACT_P,
                                             pXL + 1 * (size_t)ACT_P);
    convert_act_kernel<<<ACT_P / 256, 256>>>(value, pXH + 2 * (size_t)ACT_P,
                                             pXL + 2 * (size_t)ACT_P);

    // 3) Q/K/V projections (3xBF16 pre-packed), one merged launch
    cudaFuncSetAttribute(proj_qkv_kernel,
                         cudaFuncAttributeMaxDynamicSharedMemorySize, PROJ_SMEM);
    cudaFuncSetAttribute(proj_out_kernel,
                         cudaFuncAttributeMaxDynamicSharedMemorySize, PROJ_SMEM);
    dim3 gq(DMODEL / 128, MROWS / 128, 3);
    proj_qkv_kernel<<<gq, 256, PROJ_SMEM>>>(pXH, pXL, pWH, pWL,
                                            bq, bk, bv, pQ, pK, pV);

    // 4) fused masked attention (R12)
    cudaFuncSetAttribute(attn_kernel, cudaFuncAttributeMaxDynamicSharedMemorySize,
                         ATTN_SMEM);
    attn_kernel<<<dim3(NSEQ / 128, BATCH * NHEAD), 256, ATTN_SMEM>>>();

    // 5) convert context, then output projection -> d_out
    convert_act_kernel<<<ACT_P / 256, 256>>>(pC, pXH, pXL);
    dim3 go(DMODEL / 128, MROWS / 128);
    proj_out_kernel<<<go, 256, PROJ_SMEM>>>(pXH, pXL, pWH + 3 * W_P,
                                            pWL + 3 * W_P, bo, out);
}

// round 16
// speedup vs baseline: 1.1364x; 1.1364x over previous
#include <cuda_runtime.h>
#include <cstdint>
#include <cstddef>

// Problem constants
#define BATCH  4
#define NSEQ   2048
#define DMODEL 1024
#define NHEAD  16
#define DKH    64
#define MROWS  (BATCH * NSEQ)   // 8192
#define NEGVAL (-1e11f)

// ---------------- scratch (device globals; no allocation allowed) ----------
__device__ float    g_Q[BATCH * NHEAD * NSEQ * DKH];   // (B,H,N,DK)
__device__ float    g_K[BATCH * NHEAD * NSEQ * DKH];
__device__ float    g_V[BATCH * NHEAD * NSEQ * DKH];
__device__ float    g_C[BATCH * NSEQ * DMODEL];        // attention context (B,N,D)
__device__ unsigned g_pmask[BATCH * NSEQ * NSEQ / 32]; // bit-packed mask

// ---------------- helpers ---------------------------------------------------
__device__ __forceinline__ uint32_t f2tf32(float x) {
    uint32_t r;
    asm("cvt.rna.tf32.f32 %0, %1;" : "=r"(r) : "f"(x));
    return r;
}

__device__ __forceinline__ void mma_tf32(float* c, const uint32_t* a,
                                         uint32_t b0, uint32_t b1) {
    asm volatile(
        "mma.sync.aligned.m16n8k8.row.col.f32.tf32.tf32.f32 "
        "{%0,%1,%2,%3}, {%4,%5,%6,%7}, {%8,%9}, {%0,%1,%2,%3};"
        : "+f"(c[0]), "+f"(c[1]), "+f"(c[2]), "+f"(c[3])
        : "r"(a[0]), "r"(a[1]), "r"(a[2]), "r"(a[3]), "r"(b0), "r"(b1));
}

// fp16 m16n8k16: 4 A regs (f16x2), 2 B regs, f32 accum.  D layout == m16n8.
__device__ __forceinline__ void mma_f16(float* c, const uint32_t* a,
                                        uint32_t b0, uint32_t b1) {
    asm volatile(
        "mma.sync.aligned.m16n8k16.row.col.f32.f16.f16.f32 "
        "{%0,%1,%2,%3}, {%4,%5,%6,%7}, {%8,%9}, {%0,%1,%2,%3};"
        : "+f"(c[0]), "+f"(c[1]), "+f"(c[2]), "+f"(c[3])
        : "r"(a[0]), "r"(a[1]), "r"(a[2]), "r"(a[3]), "r"(b0), "r"(b1));
}

// pack two floats to f16x2: lo_val -> low half (lower k), hi_val -> high half
// (same operand convention as the R13-validated bf16x2 pack)
__device__ __forceinline__ uint32_t pack_f16x2(float lo_val, float hi_val) {
    uint32_t r;
    asm("cvt.rn.f16x2.f32 %0, %1, %2;" : "=r"(r) : "f"(hi_val), "f"(lo_val));
    return r;
}

__device__ __forceinline__ void cp16(uint32_t dst, const float* src) {
    asm volatile("cp.async.ca.shared.global [%0], [%1], 16;\n"
                 :: "r"(dst), "l"(src));
}
__device__ __forceinline__ void cp_commit() {
    asm volatile("cp.async.commit_group;\n");
}
template <int N>
__device__ __forceinline__ void cp_wait() {
    asm volatile("cp.async.wait_group %0;\n" :: "n"(N));
}
__device__ __forceinline__ uint32_t smem_u32(const void* p) {
    return (uint32_t)__cvta_generic_to_shared(p);
}

// ---------------- mask bit-pack: 67MB int32 -> 2MB bits --------------------
__global__ void pack_mask_kernel(const int* __restrict__ mask) {
    int idx = blockIdx.x * blockDim.x + threadIdx.x;
    unsigned bit = (mask[idx] != 0) ? 1u : 0u;
    unsigned w = __ballot_sync(0xffffffffu, bit);
    if ((threadIdx.x & 31) == 0) g_pmask[idx >> 5] = w;
}

// ---------------- projection GEMM core: 2xFP16(k16) + cp.async pipeline -----
// C(8192x1024) = A @ W + bias.  Block tile 128x128, BK=16, 256 threads (8 warps,
// 2x4 warp grid, warp tile 64x32).  Raw fp32 staged (R12-proven pipeline).
// Per BK=16 tile: ONE m16n8k16 fp16 step, 2 products (aH*bH + aH*bL) where
// hi = exact mantissa-mask split (11-bit, == tf32 mantissa) -> same error
// structure as R12's 2xTF32 at HALF the mma instruction count.
#define AST 20    // A smem row stride (floats)
#define BST 136   // B smem row stride (floats)
#define FMASK 0xFFFFE000u   // keep sign+exp+10 explicit mantissa bits

template <bool SPLIT>
__device__ __forceinline__ void proj_core(const float* __restrict__ A,
                                          const float* __restrict__ W,
                                          const float* __restrict__ bias,
                                          float* __restrict__ out) {
    __shared__ float sA[2][128 * AST];   // [m][k] raw fp32
    __shared__ float sB[2][16 * BST];    // [k][n] raw fp32

    const int tid = threadIdx.x;
    const int w = tid >> 5, l = tid & 31;
    const int lg = l >> 2, lk = l & 3;
    const int wm = (w >> 2) * 64;       // 0,64
    const int wn = (w & 3) * 32;        // 0,32,64,96
    const int m0 = blockIdx.y * 128, n0 = blockIdx.x * 128;

    const uint32_t sAaddr0 = smem_u32(&sA[0][0]);
    const uint32_t sAaddr1 = smem_u32(&sA[1][0]);
    const uint32_t sBaddr0 = smem_u32(&sB[0][0]);
    const uint32_t sBaddr1 = smem_u32(&sB[1][0]);

    const int ac0 = tid, ac1 = tid + 256;
    const int ar0 = ac0 >> 2, ao0 = (ac0 & 3) * 4;
    const int ar1 = ac1 >> 2, ao1 = (ac1 & 3) * 4;
    const int bc0 = tid, bc1 = tid + 256;
    const int br0 = bc0 >> 5, bo0 = (bc0 & 31) * 4;
    const int br1 = bc1 >> 5, bo1 = (bc1 & 31) * 4;

    auto load_tile = [&](int kt, int buf) {
        uint32_t sa = buf ? sAaddr1 : sAaddr0;
        uint32_t sb = buf ? sBaddr1 : sBaddr0;
        cp16(sa + (ar0 * AST + ao0) * 4, A + (size_t)(m0 + ar0) * DMODEL + kt + ao0);
        cp16(sa + (ar1 * AST + ao1) * 4, A + (size_t)(m0 + ar1) * DMODEL + kt + ao1);
        cp16(sb + (br0 * BST + bo0) * 4, W + (size_t)(kt + br0) * DMODEL + n0 + bo0);
        cp16(sb + (br1 * BST + bo1) * 4, W + (size_t)(kt + br1) * DMODEL + n0 + bo1);
        cp_commit();
    };

    float c[4][4][4];
#pragma unroll
    for (int mi = 0; mi < 4; ++mi)
#pragma unroll
        for (int nj = 0; nj < 4; ++nj)
#pragma unroll
            for (int t = 0; t < 4; ++t) c[mi][nj][t] = 0.f;

    load_tile(0, 0);
    load_tile(16, 1);

    for (int it = 0; it < DMODEL / 16; ++it) {
        const float* cA = sA[it & 1];
        const float* cB = sB[it & 1];
        cp_wait<1>();
        __syncthreads();

        // ---- A fragments: fp16x2 via direct round (A single-rounded) ----
        uint32_t aH[4][4];
#pragma unroll
        for (int mi = 0; mi < 4; ++mi) {
            int mb = wm + 16 * mi + lg;
            float2 v0 = *(const float2*)&cA[mb * AST + 2 * lk];
            float2 v1 = *(const float2*)&cA[(mb + 8) * AST + 2 * lk];
            float2 v2 = *(const float2*)&cA[mb * AST + 2 * lk + 8];
            float2 v3 = *(const float2*)&cA[(mb + 8) * AST + 2 * lk + 8];
            aH[mi][0] = pack_f16x2(v0.x, v0.y);
            aH[mi][1] = pack_f16x2(v1.x, v1.y);
            aH[mi][2] = pack_f16x2(v2.x, v2.y);
            aH[mi][3] = pack_f16x2(v3.x, v3.y);
        }

        // ---- B split hi/lo (mask-truncation, exact residual) + mma ----
#pragma unroll
        for (int nj = 0; nj < 4; ++nj) {
            int nb = wn + 8 * nj + lg;
            float b00 = cB[(2 * lk) * BST + nb];
            float b01 = cB[(2 * lk + 1) * BST + nb];
            float b10 = cB[(2 * lk + 8) * BST + nb];
            float b11 = cB[(2 * lk + 9) * BST + nb];
            float h00 = __uint_as_float(__float_as_uint(b00) & FMASK);
            float h01 = __uint_as_float(__float_as_uint(b01) & FMASK);
            float h10 = __uint_as_float(__float_as_uint(b10) & FMASK);
            float h11 = __uint_as_float(__float_as_uint(b11) & FMASK);
            uint32_t bH0 = pack_f16x2(h00, h01);
            uint32_t bH1 = pack_f16x2(h10, h11);
            uint32_t bL0 = pack_f16x2(b00 - h00, b01 - h01);
            uint32_t bL1 = pack_f16x2(b10 - h10, b11 - h11);
#pragma unroll
            for (int mi = 0; mi < 4; ++mi) {
                mma_f16(c[mi][nj], aH[mi], bH0, bH1);
                mma_f16(c[mi][nj], aH[mi], bL0, bL1);
            }
        }

        __syncthreads();
        if (it + 2 < DMODEL / 16) load_tile((it + 2) * 16, it & 1);
        else cp_commit();
    }

    // epilogue: bias + store (optionally remapped to (B,H,N,DK))
#pragma unroll
    for (int mi = 0; mi < 4; ++mi) {
#pragma unroll
        for (int nj = 0; nj < 4; ++nj) {
            int col = n0 + wn + 8 * nj + 2 * lk;
            float b0 = __ldg(&bias[col]), b1 = __ldg(&bias[col + 1]);
#pragma unroll
            for (int half = 0; half < 2; ++half) {
                int m = m0 + wm + 16 * mi + lg + 8 * half;
                float2 v;
                v.x = c[mi][nj][2 * half + 0] + b0;
                v.y = c[mi][nj][2 * half + 1] + b1;
                size_t idx;
                if (SPLIT) {
                    int b = m >> 11, row = m & 2047;
                    int h = col >> 6, dk = col & 63;
                    idx = (((size_t)(b * NHEAD + h) * NSEQ + row) * DKH + dk);
                } else {
                    idx = (size_t)m * DMODEL + col;
                }
                *(float2*)&out[idx] = v;
            }
        }
    }
}

__global__ __launch_bounds__(256)
void proj_qkv_kernel(const float* __restrict__ q, const float* __restrict__ k,
                     const float* __restrict__ v,
                     const float* __restrict__ Wq, const float* __restrict__ Wk,
                     const float* __restrict__ Wv,
                     const float* __restrict__ bq, const float* __restrict__ bk,
                     const float* __restrict__ bv,
                     float* __restrict__ oq, float* __restrict__ ok,
                     float* __restrict__ ov) {
    const float *A, *W, *bias;
    float* out;
    if (blockIdx.z == 0)      { A = q; W = Wq; bias = bq; out = oq; }
    else if (blockIdx.z == 1) { A = k; W = Wk; bias = bk; out = ok; }
    else                      { A = v; W = Wv; bias = bv; out = ov; }
    proj_core<true>(A, W, bias, out);
}

__global__ __launch_bounds__(256)
void proj_out_kernel(const float* __restrict__ A, const float* __restrict__ W,
                     const float* __restrict__ bias, float* __restrict__ out) {
    proj_core<false>(A, W, bias, out);
}

// ---------------- fused masked flash attention (R12 best, unchanged) --------
#define QPAD 68
#define KST  68
#define VST  72
#define ATTN_SMEM (128 * QPAD * 4 + 2 * 64 * KST * 4 + 2 * 64 * VST * 4 + 256 * 4)
__global__ __launch_bounds__(256)
void attn_kernel() {
    extern __shared__ char smraw[];
    uint32_t* Qs = (uint32_t*)smraw;                       // [128][QPAD] tf32
    float*    Ps = (float*)smraw;                          // aliases Qs
    float*    Kb = (float*)(smraw + 128 * QPAD * 4);       // [2][64][KST]
    float*    Vb = (float*)(smraw + 128 * QPAD * 4 + 2 * 64 * KST * 4);
    unsigned* Ms = (unsigned*)(smraw + 128 * QPAD * 4 + 2 * 64 * KST * 4
                               + 2 * 64 * VST * 4);        // [128][2]

    const int tid = threadIdx.x;
    const int w = tid >> 5, l = tid & 31;
    const int lg = l >> 2, lk = l & 3;
    const int rb = w * 16;
    const int bh = blockIdx.y;
    const int b = bh >> 4;
    const int h = bh & 15;
    const int q0 = blockIdx.x * 128;

    const float* Qg = g_Q + ((size_t)bh * NSEQ + q0) * DKH;
    const float* Kg = g_K + (size_t)bh * NSEQ * DKH;
    const float* Vg = g_V + (size_t)bh * NSEQ * DKH;

    const uint32_t KbAddr = smem_u32(Kb);
    const uint32_t VbAddr = smem_u32(Vb);

    auto load_kv = [&](int kt, int buf) {
        const float* Ksrc = Kg + (size_t)kt * 64 * DKH;
        const float* Vsrc = Vg + (size_t)kt * 64 * DKH;
        uint32_t kbase = KbAddr + buf * (64 * KST * 4);
        uint32_t vbase = VbAddr + buf * (64 * VST * 4);
#pragma unroll
        for (int i = 0; i < 4; ++i) {
            int ck = tid + 256 * i;
            int row = ck >> 4, c4 = (ck & 15) * 4;
            cp16(kbase + (row * KST + c4) * 4, Ksrc + row * DKH + c4);
            cp16(vbase + (row * VST + c4) * 4, Vsrc + row * DKH + c4);
        }
        cp_commit();
    };

#pragma unroll
    for (int i = 0; i < 8; ++i) {
        int v = tid + 256 * i;
        int row = v >> 4, d4 = (v & 15) * 4;
        float4 q = *(const float4*)(Qg + (size_t)row * DKH + d4);
        Qs[row * QPAD + d4 + 0] = f2tf32(q.x);
        Qs[row * QPAD + d4 + 1] = f2tf32(q.y);
        Qs[row * QPAD + d4 + 2] = f2tf32(q.z);
        Qs[row * QPAD + d4 + 3] = f2tf32(q.w);
    }
    __syncthreads();

    load_kv(0, 0);
    load_kv(1, 1);

    uint32_t qf[8][4];
#pragma unroll
    for (int ks = 0; ks < 8; ++ks) {
        qf[ks][0] = Qs[(rb + lg) * QPAD + ks * 8 + lk];
        qf[ks][1] = Qs[(rb + lg + 8) * QPAD + ks * 8 + lk];
        qf[ks][2] = Qs[(rb + lg) * QPAD + ks * 8 + lk + 4];
        qf[ks][3] = Qs[(rb + lg + 8) * QPAD + ks * 8 + lk + 4];
    }

    float m_run[2] = {-1e30f, -1e30f};
    float l_run[2] = {0.f, 0.f};

    float o[8][4];
#pragma unroll
    for (int nj = 0; nj < 8; ++nj)
#pragma unroll
        for (int t = 0; t < 4; ++t) o[nj][t] = 0.f;

    const int maskRowBase = b * NSEQ + q0;

    for (int kt = 0; kt < NSEQ / 64; ++kt) {
        float* K0 = Kb + (kt & 1) * (64 * KST);
        float* V0 = Vb + (kt & 1) * (64 * VST);

        cp_wait<1>();
        __syncthreads();

#pragma unroll
        for (int i = 0; i < 4; ++i) {
            int p = tid + 256 * i;
            int row = p >> 4, d4 = (p & 15) * 4;
            float4* ka = (float4*)&K0[row * KST + d4];
            float4 kv = *ka;
            uint4 kc = make_uint4(f2tf32(kv.x), f2tf32(kv.y), f2tf32(kv.z), f2tf32(kv.w));
            *(uint4*)ka = kc;
            float4* va = (float4*)&V0[row * VST + d4];
            float4 vv = *va;
            uint4 vc = make_uint4(f2tf32(vv.x), f2tf32(vv.y), f2tf32(vv.z), f2tf32(vv.w));
            *(uint4*)va = vc;
        }
        Ms[tid] = g_pmask[(size_t)(maskRowBase + (tid >> 1)) * (NSEQ / 32)
                          + kt * 2 + (tid & 1)];
        __syncthreads();

        float sc[8][4];
#pragma unroll
        for (int nj = 0; nj < 8; ++nj)
#pragma unroll
            for (int t = 0; t < 4; ++t) sc[nj][t] = 0.f;
#pragma unroll
        for (int ks = 0; ks < 8; ++ks) {
#pragma unroll
            for (int nj = 0; nj < 8; ++nj) {
                int nb = 8 * nj + lg;
                uint32_t b0 = __float_as_uint(K0[nb * KST + ks * 8 + lk]);
                uint32_t b1 = __float_as_uint(K0[nb * KST + ks * 8 + lk + 4]);
                mma_tf32(sc[nj], qf[ks], b0, b1);
            }
        }

#pragma unroll
        for (int r = 0; r < 2; ++r) {
            int row = rb + lg + 8 * r;
            unsigned mwA = Ms[row * 2], mwB = Ms[row * 2 + 1];
            int t0 = 2 * r;
            float rm = -1e30f;
#pragma unroll
            for (int nj = 0; nj < 8; ++nj) {
                int col = 8 * nj + 2 * lk;
                unsigned word = (nj < 4) ? mwA : mwB;
                float v0 = ((word >> (col & 31)) & 1u) ? sc[nj][t0] * 0.125f : NEGVAL;
                float v1 = ((word >> ((col + 1) & 31)) & 1u) ? sc[nj][t0 + 1] * 0.125f : NEGVAL;
                sc[nj][t0] = v0;
                sc[nj][t0 + 1] = v1;
                rm = fmaxf(rm, fmaxf(v0, v1));
            }
            rm = fmaxf(rm, __shfl_xor_sync(0xffffffffu, rm, 1));
            rm = fmaxf(rm, __shfl_xor_sync(0xffffffffu, rm, 2));
            float mn = fmaxf(m_run[r], rm);
            float corr = __expf(m_run[r] - mn);
            m_run[r] = mn;
            float ls = 0.f;
#pragma unroll
            for (int nj = 0; nj < 8; ++nj) {
                float p0 = __uint_as_float(f2tf32(__expf(sc[nj][t0] - mn)));
                float p1 = __uint_as_float(f2tf32(__expf(sc[nj][t0 + 1] - mn)));
                sc[nj][t0] = p0;
                sc[nj][t0 + 1] = p1;
                ls += p0 + p1;
            }
            ls += __shfl_xor_sync(0xffffffffu, ls, 1);
            ls += __shfl_xor_sync(0xffffffffu, ls, 2);
            l_run[r] = l_run[r] * corr + ls;
#pragma unroll
            for (int nj = 0; nj < 8; ++nj) {
                o[nj][t0] *= corr;
                o[nj][t0 + 1] *= corr;
            }
#pragma unroll
            for (int nj = 0; nj < 8; ++nj)
                *(float2*)&Ps[row * QPAD + 8 * nj + 2 * lk] =
                    make_float2(sc[nj][t0], sc[nj][t0 + 1]);
        }
        __syncwarp();

#pragma unroll
        for (int ks = 0; ks < 8; ++ks) {
            uint32_t af[4];
            af[0] = __float_as_uint(Ps[(rb + lg) * QPAD + ks * 8 + lk]);
            af[1] = __float_as_uint(Ps[(rb + lg + 8) * QPAD + ks * 8 + lk]);
            af[2] = __float_as_uint(Ps[(rb + lg) * QPAD + ks * 8 + lk + 4]);
            af[3] = __float_as_uint(Ps[(rb + lg + 8) * QPAD + ks * 8 + lk + 4]);
#pragma unroll
            for (int nj = 0; nj < 8; ++nj) {
                int nb = 8 * nj + lg;
                uint32_t b0 = __float_as_uint(V0[(ks * 8 + lk) * VST + nb]);
                uint32_t b1 = __float_as_uint(V0[(ks * 8 + lk + 4) * VST + nb]);
                mma_tf32(o[nj], af, b0, b1);
            }
        }

        __syncthreads();
        if (kt + 2 < NSEQ / 64) load_kv(kt + 2, kt & 1);
        else cp_commit();
    }

    float inv0 = 1.0f / l_run[0], inv1 = 1.0f / l_run[1];
    float* Cg = g_C + ((size_t)(b * NSEQ + q0)) * DMODEL + h * DKH;
#pragma unroll
    for (int nj = 0; nj < 8; ++nj) {
        int col = 8 * nj + 2 * lk;
        *(float2*)&Cg[(size_t)(rb + lg) * DMODEL + col] =
            make_float2(o[nj][0] * inv0, o[nj][1] * inv0);
        *(float2*)&Cg[(size_t)(rb + lg + 8) * DMODEL + col] =
            make_float2(o[nj][2] * inv1, o[nj][3] * inv1);
    }
}

// ---------------- launch ----------------------------------------------------
extern "C" void kernel_launch(void* const* d_in, const int* in_sizes, int n_in,
                              void* d_out, int out_size) {
    const float* query = (const float*)d_in[0];
    const float* key   = (const float*)d_in[1];
    const float* value = (const float*)d_in[2];
    const int*   mask  = (const int*)d_in[3];
    const float* Wq = (const float*)d_in[4];
    const float* bq = (const float*)d_in[5];
    const float* Wk = (const float*)d_in[6];
    const float* bk = (const float*)d_in[7];
    const float* Wv = (const float*)d_in[8];
    const float* bv = (const float*)d_in[9];
    const float* Wo = (const float*)d_in[10];
    const float* bo = (const float*)d_in[11];
    float* out = (float*)d_out;

    float *pQ, *pK, *pV, *pC;
    cudaGetSymbolAddress((void**)&pQ, g_Q);
    cudaGetSymbolAddress((void**)&pK, g_K);
    cudaGetSymbolAddress((void**)&pV, g_V);
    cudaGetSymbolAddress((void**)&pC, g_C);

    // 1) pack mask to bits
    pack_mask_kernel<<<(BATCH * NSEQ * NSEQ) / 256, 256>>>(mask);

    // 2) Q/K/V projections (2xFP16 k16, cp.async pipelined), one merged launch
    dim3 gq(DMODEL / 128, MROWS / 128, 3);
    proj_qkv_kernel<<<gq, 256>>>(query, key, value, Wq, Wk, Wv,
                                 bq, bk, bv, pQ, pK, pV);

    // 3) fused masked attention (tf32 mma, fragment softmax, cp.async KV)
    cudaFuncSetAttribute(attn_kernel, cudaFuncAttributeMaxDynamicSharedMemorySize,
                         ATTN_SMEM);
    attn_kernel<<<dim3(NSEQ / 128, BATCH * NHEAD), 256, ATTN_SMEM>>>();

    // 4) output projection (2xFP16 k16, cp.async pipelined) -> d_out
    dim3 go(DMODEL / 128, MROWS / 128);
    proj_out_kernel<<<go, 256>>>(pC, Wo, bo, out);
}